// round 17
// baseline (speedup 1.0000x reference)
#include <cuda_runtime.h>
#include <cuda_bf16.h>
#include <cstdint>

// Grapher round 17: single fused kernel (grid 128 x 1024).
//   scan -> [3-tile means (576 thr) || Wm->bf16 hi/lo cvt + W1 prefetch (448 thr)]
//   -> combine -> GEMM1 fp32 FFMA2 -> pair build (X hi/lo straight into smem)
//   -> layer-1 mma.sync (warps 0-18) || W2->bf16 cvt into freed P region (warps 19-31)
//   -> re-split epilogue -> layer-2 mma.sync -> out.
// No cp.async, no global scratch images, no extra launches.

#define B_   128
#define S_   1024
#define H_   768
#define C_   150
#define NN   8
#define SEPID 3
#define NTHR 1024

typedef unsigned long long u64;

// ---- smem layout (bytes) ----
// [0,      46208)  Wm hi  [n][k] bf16 (pads zero)        - permanent
// [46208,  92416)  Wm lo                                  - permanent
// [92416, 184832)  P: means partials (74112) / GEMM1 partials (38400) -> W2 hi+lo
// [184832,209408)  meansT (24576)  -> X hi [184832,204288)
// [204288,223744)                      X lo
// [223744,228608)  sG  8*152 f32
// [228608,229216)  sB1 152 f32
// [229216,229280)  sBnd 16 int
#define O_WMHI  0
#define O_WMLO  46208
#define O_W2HI  92416
#define O_W2LO  138624
#define O_X     184832
#define O_XLO   204288
#define F_P     23104      // float offset of P region (byte 92416)
#define F_MT    46208      // float offset of meansT (byte 184832)
#define F_G     55936
#define F_B1    57152
#define F_BND   57304
#define SMEM_BYTES 229280

__device__ __forceinline__ uint32_t sptr(const void* p) {
    return (uint32_t)__cvta_generic_to_shared(p);
}
__device__ __forceinline__ void ffma2(u64& d, u64 a, u64 b) {
    asm("fma.rn.f32x2 %0, %1, %2, %0;" : "+l"(d) : "l"(a), "l"(b));
}
__device__ __forceinline__ u64 add2(u64 a, u64 b) {
    u64 r; asm("add.rn.f32x2 %0, %1, %2;" : "=l"(r) : "l"(a), "l"(b)); return r;
}
__device__ __forceinline__ u64 dup2(float x) {
    u64 r; asm("mov.b64 %0, {%1, %1};" : "=l"(r) : "f"(x)); return r;
}
__device__ __forceinline__ void unpack2(u64 v, float& lo, float& hi) {
    asm("mov.b64 {%0, %1}, %2;" : "=f"(lo), "=f"(hi) : "l"(v));
}
__device__ __forceinline__ u64 lds64(uint32_t a) {
    u64 v; asm volatile("ld.shared.u64 %0, [%1];" : "=l"(v) : "r"(a)); return v;
}
__device__ __forceinline__ void lds_v2(uint32_t a, u64& x, u64& y) {
    asm volatile("ld.shared.v2.u64 {%0, %1}, [%2];" : "=l"(x), "=l"(y) : "r"(a));
}
__device__ __forceinline__ void sts64(uint32_t a, u64 v) {
    asm volatile("st.shared.u64 [%0], %1;" :: "r"(a), "l"(v) : "memory");
}
__device__ __forceinline__ uint32_t lds_u32(uint32_t a) {
    uint32_t v; asm volatile("ld.shared.b32 %0, [%1];" : "=r"(v) : "r"(a)); return v;
}
__device__ __forceinline__ void sts_u32(uint32_t a, uint32_t v) {
    asm volatile("st.shared.b32 [%0], %1;" :: "r"(a), "r"(v) : "memory");
}
__device__ __forceinline__ void sts_u16(uint32_t a, unsigned short v) {
    asm volatile("st.shared.u16 [%0], %1;" :: "r"(a), "h"(v) : "memory");
}
__device__ __forceinline__ unsigned short f2bf(float x) {
    __nv_bfloat16 h = __float2bfloat16_rn(x);
    return *reinterpret_cast<unsigned short*>(&h);
}
__device__ __forceinline__ float bf2f(unsigned short u) {
    __nv_bfloat16 h = *reinterpret_cast<__nv_bfloat16*>(&u);
    return __bfloat162float(h);
}
__device__ __forceinline__ uint32_t pack_bf2(float a, float b) {
    return (uint32_t)f2bf(a) | ((uint32_t)f2bf(b) << 16);
}

__device__ __forceinline__ void mma8(float c[4], uint32_t a0, uint32_t a1, uint32_t b0) {
    asm volatile(
        "mma.sync.aligned.m16n8k8.row.col.f32.bf16.bf16.f32 "
        "{%0,%1,%2,%3}, {%4,%5}, {%6}, {%0,%1,%2,%3};"
        : "+f"(c[0]), "+f"(c[1]), "+f"(c[2]), "+f"(c[3])
        : "r"(a0), "r"(a1), "r"(b0));
}
__device__ __forceinline__ void mma16(float c[4], uint32_t a0, uint32_t a1,
                                      uint32_t a2, uint32_t a3,
                                      uint32_t b0, uint32_t b1) {
    asm volatile(
        "mma.sync.aligned.m16n8k16.row.col.f32.bf16.bf16.f32 "
        "{%0,%1,%2,%3}, {%4,%5,%6,%7}, {%8,%9}, {%0,%1,%2,%3};"
        : "+f"(c[0]), "+f"(c[1]), "+f"(c[2]), "+f"(c[3])
        : "r"(a0), "r"(a1), "r"(a2), "r"(a3), "r"(b0), "r"(b1));
}

__global__ __launch_bounds__(NTHR, 1)
void grapher_fused(const int* __restrict__ ids,
                   const float* __restrict__ feat,
                   const float* __restrict__ W1, const float* __restrict__ b1,
                   const float* __restrict__ Wm, const float* __restrict__ bm,
                   const float* __restrict__ W2, const float* __restrict__ b2,
                   float* __restrict__ out)
{
    extern __shared__ float sm[];
    char* smc = (char*)sm;
    const uint32_t sb = sptr(sm);
    float* sP  = sm + F_P;
    float* sMT = sm + F_MT;
    float* sG  = sm + F_G;
    float* sB1 = sm + F_B1;
    int*   sBnd = (int*)(sm + F_BND);

    const int tid = threadIdx.x;
    const int b   = blockIdx.x;
    const uint32_t mt_b = sptr(sMT);
    const uint32_t pp_b = sptr(sP);

    // ---------- phase 1: scan (warp 0) + b1 load ----------
    if (tid < 32) {
        const int lane = tid;
        if (lane < 16) sBnd[lane] = S_;
        __syncwarp();
        const int4* rp = (const int4*)(ids + (size_t)b * S_) + lane * 8;
        int4 v[8];
        int cnt = 0;
#pragma unroll
        for (int q = 0; q < 8; q++) {
            v[q] = rp[q];
            cnt += (v[q].x == SEPID) + (v[q].y == SEPID) +
                   (v[q].z == SEPID) + (v[q].w == SEPID);
        }
        int pre = cnt;
#pragma unroll
        for (int off = 1; off < 32; off <<= 1) {
            int t = __shfl_up_sync(0xffffffffu, pre, off);
            if (lane >= off) pre += t;
        }
        int run = pre - cnt;
#pragma unroll
        for (int q = 0; q < 8; q++) {
            int base = lane * 32 + q * 4;
            if (v[q].x == SEPID) { run++; if (run <= NN) sBnd[run] = base + 0; }
            if (v[q].y == SEPID) { run++; if (run <= NN) sBnd[run] = base + 1; }
            if (v[q].z == SEPID) { run++; if (run <= NN) sBnd[run] = base + 2; }
            if (v[q].w == SEPID) { run++; if (run <= NN) sBnd[run] = base + 3; }
        }
    } else if (tid >= 64 && tid < 64 + 152) {
        int i = tid - 64;
        sB1[i] = (i < C_) ? b1[i] : 0.f;
    }
    __syncthreads();

    // ---------- phase 2: means (tid<576, 3 tiles) || Wm cvt + W1 prefetch ----
    if (tid < 576) {
        const int tg  = tid / 192;
        const int col = tid - tg * 192;
        const int T   = sBnd[NN];
        const int tb0 = (T * tg) / 3;
        const int tb1 = (T * (tg + 1)) / 3;
        const float4* f4 = (const float4*)(feat + (size_t)b * S_ * H_) + col;
        float* P = sP + tg * 6176 + col * 4;
#pragma unroll 1
        for (int n = 0; n < NN; n++) {
            int lo = (n == 0) ? 0 : sBnd[n] + 1;
            int hi = sBnd[n + 1];
            if (lo < tb0) lo = tb0;
            if (hi > tb1) hi = tb1;
            float4 a0 = make_float4(0.f, 0.f, 0.f, 0.f), a1 = a0, a2 = a0, a3 = a0;
            int t = lo;
            for (; t + 3 < hi; t += 4) {
                float4 v0 = f4[(t + 0) * 192];
                float4 v1 = f4[(t + 1) * 192];
                float4 v2 = f4[(t + 2) * 192];
                float4 v3 = f4[(t + 3) * 192];
                a0.x += v0.x; a0.y += v0.y; a0.z += v0.z; a0.w += v0.w;
                a1.x += v1.x; a1.y += v1.y; a1.z += v1.z; a1.w += v1.w;
                a2.x += v2.x; a2.y += v2.y; a2.z += v2.z; a2.w += v2.w;
                a3.x += v3.x; a3.y += v3.y; a3.z += v3.z; a3.w += v3.w;
            }
            for (; t < hi; t++) {
                float4 v = f4[t * 192];
                a0.x += v.x; a0.y += v.y; a0.z += v.z; a0.w += v.w;
            }
            float4 s;
            s.x = (a0.x + a1.x) + (a2.x + a3.x);
            s.y = (a0.y + a1.y) + (a2.y + a3.y);
            s.z = (a0.z + a1.z) + (a2.z + a3.z);
            s.w = (a0.w + a1.w) + (a2.w + a3.w);
            *(float4*)(P + n * 772) = s;
        }
    } else {
        // 448 spare threads: Wm fp32 [k][n] -> smem bf16 hi/lo [n][k] (idx = n*152+k)
        for (int idx = tid - 576; idx < 152 * 152; idx += 448) {
            int n = idx / 152, k = idx - n * 152;
            float v = (k < C_ && n < C_) ? __ldg(Wm + k * C_ + n) : 0.f;
            unsigned short h = f2bf(v);
            sts_u16(sb + O_WMHI + (uint32_t)idx * 2u, h);
            sts_u16(sb + O_WMLO + (uint32_t)idx * 2u, f2bf(v - bf2f(h)));
        }
        // then: L2-prefetch W1 for GEMM1
        const float4* w4 = (const float4*)W1;
        for (int i = tid - 576; i < (H_ * C_) / 4; i += 448)
            asm volatile("prefetch.global.L2 [%0];" :: "l"(w4 + i));
    }
    __syncthreads();

    // ---------- phase 3: combine tiles + 1/len -> meansT[k][8] ----------
    if (tid < H_) {
        float inv[8];
#pragma unroll
        for (int n = 0; n < NN; n++) {
            int lo = (n == 0) ? 0 : sBnd[n] + 1;
            int len = sBnd[n + 1] - lo;
            if (len < 1) len = 1;
            inv[n] = 1.0f / (float)len;
        }
        const float* P = sP + tid;
#pragma unroll
        for (int n = 0; n < NN; n++) {
            float s = (P[n * 772] + P[6176 + n * 772]) + P[12352 + n * 772];
            sMT[tid * 8 + n] = s * inv[n];
        }
    }
    __syncthreads();                      // P region free for GEMM1 partials

    // ---------- phase 4: GEMM1 fp32 FFMA2 ----------
    u64 g_acc[2][4];
    int ks1 = 0, cpair = 0;
    if (tid < 600) {
        ks1 = tid / 75; cpair = tid - ks1 * 75;
#pragma unroll
        for (int cc = 0; cc < 2; cc++)
#pragma unroll
            for (int q = 0; q < 4; q++) g_acc[cc][q] = 0ull;
        const float2* wrow = (const float2*)(W1 + (size_t)(ks1 * 96) * C_) + cpair;
#pragma unroll 4
        for (int kk = 0; kk < 96; kk++) {
            int k = ks1 * 96 + kk;
            float2 w = __ldg(wrow + kk * 75);
            u64 dw0 = dup2(w.x), dw1 = dup2(w.y);
            u64 m01, m23, m45, m67;
            uint32_t ma = mt_b + (uint32_t)(k * 8) * 4u;
            lds_v2(ma, m01, m23);
            lds_v2(ma + 16u, m45, m67);
            ffma2(g_acc[0][0], m01, dw0); ffma2(g_acc[0][1], m23, dw0);
            ffma2(g_acc[0][2], m45, dw0); ffma2(g_acc[0][3], m67, dw0);
            ffma2(g_acc[1][0], m01, dw1); ffma2(g_acc[1][1], m23, dw1);
            ffma2(g_acc[1][2], m45, dw1); ffma2(g_acc[1][3], m67, dw1);
        }
    }
    __syncthreads();
    if (tid < 600) {
#pragma unroll
        for (int cc = 0; cc < 2; cc++)
#pragma unroll
            for (int q = 0; q < 4; q++)
                sts64(pp_b + (uint32_t)(ks1 * 1200 + (cc * 4 + q) * 150 + 2 * cpair) * 4u,
                      g_acc[cc][q]);
    }
    __syncthreads();
    if (tid < 600) {
        u64 s = lds64(pp_b + (uint32_t)(2 * tid) * 4u);
#pragma unroll
        for (int k8 = 1; k8 < 8; k8++)
            s = add2(s, lds64(pp_b + (uint32_t)(k8 * 1200 + 2 * tid) * 4u));
        int e = tid / 75, cp2 = tid - e * 75;
        int cc = e >> 2, q = e & 3, c = 2 * cp2 + cc;
        float lo, hi; unpack2(s, lo, hi);
        sG[(2 * q + 0) * 152 + c] = lo;
        sG[(2 * q + 1) * 152 + c] = hi;
    }
    __syncthreads();                      // P free again (W2 dest), MT dead (X dest)

    // ---------- phase 5: pair build -> X hi/lo in smem ----------
    {
        const int p  = tid >> 4;          // 0..63
        const int cs = tid & 15;
        const int i  = p >> 3, j = p & 7;
#pragma unroll
        for (int m = 0; m < 5; m++) {
            int c = cs * 10 + 2 * m;
            if (c < 152) {
                float v0 = 0.f, v1 = 0.f;
                if (c < C_)
                    v0 = fmaxf(sG[i * 152 + c] - sG[j * 152 + c] + sB1[c], 0.f);
                if (c + 1 < C_)
                    v1 = fmaxf(sG[i * 152 + c + 1] - sG[j * 152 + c + 1] + sB1[c + 1], 0.f);
                unsigned short h0 = f2bf(v0), h1 = f2bf(v1);
                uint32_t off = (uint32_t)(p * 76 + (c >> 1)) * 4u;
                sts_u32(sb + O_X   + off, (uint32_t)h0 | ((uint32_t)h1 << 16));
                sts_u32(sb + O_XLO + off, pack_bf2(v0 - bf2f(h0), v1 - bf2f(h1)));
            }
        }
    }
    __syncthreads();

    // ---------- phase 6: tensor-core layers (warps 0-18); warps 19-31 cvt W2 ----
    const int lane = tid & 31;
    const int g    = lane >> 2;
    const int tg   = lane & 3;
    const int n0   = (tid >> 5) * 8;
    const int cc0  = n0 + 2 * tg;
    const bool active = (tid < 608);

    float acc[4][4];

#pragma unroll 1
    for (int L = 0; L < 2; L++) {
        if (active) {
            const uint32_t whb = sb + (L ? O_W2HI : O_WMHI);
            const uint32_t wlb = sb + (L ? O_W2LO : O_WMLO);
            const float* bias = L ? b2 : bm;
            {
                float bv0 = (cc0 < C_)     ? __ldg(bias + cc0)     : 0.f;
                float bv1 = (cc0 + 1 < C_) ? __ldg(bias + cc0 + 1) : 0.f;
#pragma unroll
                for (int mt = 0; mt < 4; mt++) {
                    acc[mt][0] = bv0; acc[mt][1] = bv1;
                    acc[mt][2] = bv0; acc[mt][3] = bv1;
                }
            }
            const uint32_t brow = whb + (uint32_t)((n0 + g) * 304);
            const uint32_t brol = wlb + (uint32_t)((n0 + g) * 304);

#pragma unroll 1
            for (int ks = 0; ks < 9; ks++) {
                const uint32_t kb = (uint32_t)(ks * 32 + tg * 4);
                uint32_t bh0 = lds_u32(brow + kb);
                uint32_t bh1 = lds_u32(brow + kb + 16u);
                uint32_t bl0 = lds_u32(brol + kb);
                uint32_t bl1 = lds_u32(brol + kb + 16u);
#pragma unroll
                for (int mt = 0; mt < 4; mt++) {
                    uint32_t r0off = (uint32_t)((mt * 16 + g) * 304) + kb;
                    uint32_t r1off = r0off + 8u * 304u;
                    uint32_t ah0 = lds_u32(sb + O_X + r0off);
                    uint32_t ah1 = lds_u32(sb + O_X + r1off);
                    uint32_t ah2 = lds_u32(sb + O_X + r0off + 16u);
                    uint32_t ah3 = lds_u32(sb + O_X + r1off + 16u);
                    uint32_t al0 = lds_u32(sb + O_XLO + r0off);
                    uint32_t al1 = lds_u32(sb + O_XLO + r1off);
                    uint32_t al2 = lds_u32(sb + O_XLO + r0off + 16u);
                    uint32_t al3 = lds_u32(sb + O_XLO + r1off + 16u);
                    mma16(acc[mt], ah0, ah1, ah2, ah3, bh0, bh1);
                    mma16(acc[mt], ah0, ah1, ah2, ah3, bl0, bl1);
                    mma16(acc[mt], al0, al1, al2, al3, bh0, bh1);
                }
            }
            {   // k8 tail
                const uint32_t kb = (uint32_t)(288 + tg * 4);
                uint32_t bh = lds_u32(brow + kb);
                uint32_t bl = lds_u32(brol + kb);
#pragma unroll
                for (int mt = 0; mt < 4; mt++) {
                    uint32_t r0off = (uint32_t)((mt * 16 + g) * 304) + kb;
                    uint32_t r1off = r0off + 8u * 304u;
                    uint32_t ah0 = lds_u32(sb + O_X + r0off);
                    uint32_t ah1 = lds_u32(sb + O_X + r1off);
                    uint32_t al0 = lds_u32(sb + O_XLO + r0off);
                    uint32_t al1 = lds_u32(sb + O_XLO + r1off);
                    mma8(acc[mt], ah0, ah1, bh);
                    mma8(acc[mt], ah0, ah1, bl);
                    mma8(acc[mt], al0, al1, bh);
                }
            }
        } else if (L == 0) {
            // warps 19-31 (416 threads): W2 fp32 -> bf16 hi/lo into freed P region
            for (int idx = tid - 608; idx < 152 * 152; idx += 416) {
                int n = idx / 152, k = idx - n * 152;
                float v = (k < C_ && n < C_) ? __ldg(W2 + k * C_ + n) : 0.f;
                unsigned short h = f2bf(v);
                sts_u16(sb + O_W2HI + (uint32_t)idx * 2u, h);
                sts_u16(sb + O_W2LO + (uint32_t)idx * 2u, f2bf(v - bf2f(h)));
            }
        }
        __syncthreads();                  // layer done; W2 cvt ordered before L=1

        if (L == 0) {
            if (active) {
                // y = relu(acc) -> re-split into X hi/lo
#pragma unroll
                for (int mt = 0; mt < 4; mt++) {
                    int r0 = mt * 16 + g, r1 = r0 + 8;
                    float y00 = fmaxf(acc[mt][0], 0.f), y01 = fmaxf(acc[mt][1], 0.f);
                    float y10 = fmaxf(acc[mt][2], 0.f), y11 = fmaxf(acc[mt][3], 0.f);
                    unsigned short h00 = f2bf(y00), h01 = f2bf(y01);
                    unsigned short h10 = f2bf(y10), h11 = f2bf(y11);
                    uint32_t o0 = (uint32_t)(r0 * 152 + cc0) * 2u;
                    uint32_t o1 = (uint32_t)(r1 * 152 + cc0) * 2u;
                    sts_u32(sb + O_X   + o0, (uint32_t)h00 | ((uint32_t)h01 << 16));
                    sts_u32(sb + O_X   + o1, (uint32_t)h10 | ((uint32_t)h11 << 16));
                    sts_u32(sb + O_XLO + o0, pack_bf2(y00 - bf2f(h00), y01 - bf2f(h01)));
                    sts_u32(sb + O_XLO + o1, pack_bf2(y10 - bf2f(h10), y11 - bf2f(h11)));
                }
            }
            __syncthreads();
        }
    }

    // ---------- output ----------
    if (active && cc0 < C_) {
#pragma unroll
        for (int mt = 0; mt < 4; mt++) {
            int p0 = mt * 16 + g, p1 = p0 + 8;
            float* o0 = out + ((size_t)p0 * B_ + b) * C_ + cc0;
            float* o1 = out + ((size_t)p1 * B_ + b) * C_ + cc0;
            *(float2*)o0 = make_float2(acc[mt][0], acc[mt][1]);
            *(float2*)o1 = make_float2(acc[mt][2], acc[mt][3]);
        }
    }
}

extern "C" void kernel_launch(void* const* d_in, const int* in_sizes, int n_in,
                              void* d_out, int out_size)
{
    const int*   ids  = (const int*)d_in[0];
    const float* feat = (const float*)d_in[1];
    const float* W1 = (const float*)d_in[2];
    const float* b1 = (const float*)d_in[3];
    const float* Wm = (const float*)d_in[4];
    const float* bm = (const float*)d_in[5];
    const float* W2 = (const float*)d_in[6];
    const float* b2 = (const float*)d_in[7];
    float* out = (float*)d_out;

    cudaFuncSetAttribute(grapher_fused,
                         cudaFuncAttributeMaxDynamicSharedMemorySize, SMEM_BYTES);
    grapher_fused<<<B_, NTHR, SMEM_BYTES>>>(ids, feat, W1, b1, Wm, bm, W2, b2, out);
}